// round 1
// baseline (speedup 1.0000x reference)
#include <cuda_runtime.h>
#include <math.h>

#define BATCH 64
#define TSTEPS 1024
#define IND 64
#define HD 512
#define OUTD 64
#define NCTA 128
#define NTHR 256

// ---------------- persistent device state (no allocations allowed) ----------
__device__ float g_h1[2][HD * BATCH];      // layout: [k>>2][b][k&3]  (float4-friendly)
__device__ float g_h2[2][HD * BATCH];
__device__ float g_xT[TSTEPS * IND * BATCH]; // [t][k>>2][b][k&3]
__device__ unsigned g_gen;                  // barrier generation (monotonic across replays)
__device__ unsigned g_count;                // barrier arrival count (returns to 0)

// ---------------- grid-wide sense barrier (all 128 CTAs co-resident) --------
__device__ __forceinline__ void grid_barrier() {
    __syncthreads();
    if (threadIdx.x == 0) {
        __threadfence();                       // release: publish h writes
        volatile unsigned* vg = &g_gen;
        unsigned my = *vg;
        if (atomicAdd(&g_count, 1u) == NCTA - 1u) {
            g_count = 0u;                      // safe: nobody re-arrives until gen bumps
            __threadfence();
            *vg = my + 1u;
        } else {
            while (*vg == my) { }
        }
        __threadfence();                       // acquire
    }
    __syncthreads();
}

__device__ __forceinline__ float sigf(float x) { return 1.0f / (1.0f + __expf(-x)); }

// ---------------- shared memory layout (float offsets) ----------------------
#define O_WA   0        // 16 rows x 576  (W_ih1 | W_hh1) for this CTA's 16 gate rows
#define O_WB   9216     // 16 rows x 1024 (W_ih2 | W_hh2)
#define O_BA   25600    // 16 combined biases layer1
#define O_BB   25616    // 16 combined biases layer2
#define O_WO   25632    // 512: W_out row (CTAs 0..63)
#define O_BO   26144    // 1
#define O_RED  26148    // 4 x 64 reduction scratch for y head
#define SMEM_N 26404

#define DOT4(acc, v, wptr) do {                               \
    float4 w_ = *(const float4*)(wptr);                       \
    acc += (v).x * w_.x; acc += (v).y * w_.y;                 \
    acc += (v).z * w_.z; acc += (v).w * w_.w; } while (0)

// y(t) head: CTA c (<64) owns output column c; 4 threads per batch split K.
__device__ __forceinline__ void do_y(int t, const float4* __restrict__ h2v,
                                     int cblk, int b, int jj,
                                     const float* sWO, const float* sBO,
                                     float* sRed, float* __restrict__ out) {
    if (cblk < OUTD) {
        float p = 0.0f;
        const int k4b = jj * 32;
#pragma unroll 8
        for (int k4 = 0; k4 < 32; ++k4) {
            float4 v = h2v[(k4b + k4) * 64 + b];
            DOT4(p, v, sWO + (k4b + k4) * 4);
        }
        sRed[jj * 64 + b] = p;
    }
    __syncthreads();
    if (cblk < OUTD && jj == 0) {
        float y = sRed[b] + sRed[64 + b] + sRed[128 + b] + sRed[192 + b] + sBO[0];
        out[b * (TSTEPS * OUTD) + t * OUTD + cblk] = y;
    }
}

extern __shared__ float smem[];

__global__ void __launch_bounds__(NTHR, 1)
lstm_persistent_kernel(const float* __restrict__ x,
                       const float* __restrict__ Wih1, const float* __restrict__ Whh1,
                       const float* __restrict__ bih1, const float* __restrict__ bhh1,
                       const float* __restrict__ Wih2, const float* __restrict__ Whh2,
                       const float* __restrict__ bih2, const float* __restrict__ bhh2,
                       const float* __restrict__ Wout, const float* __restrict__ bout,
                       float* __restrict__ out) {
    float* sWA = smem + O_WA;
    float* sWB = smem + O_WB;
    float* sBA = smem + O_BA;
    float* sBB = smem + O_BB;
    float* sWO = smem + O_WO;
    float* sBO = smem + O_BO;
    float* sRed = smem + O_RED;

    const int tid = threadIdx.x;
    const int c   = blockIdx.x;       // CTA id: owns h columns j0..j0+3
    const int j0  = c * 4;
    const int b   = tid & 63;         // batch element (lanes 0..31 coalesce over b)
    const int jj  = tid >> 6;         // which of the 4 owned h columns

    // ---- load this CTA's weight slices into SMEM (once, persistent) ----
    for (int i = tid; i < 16 * 576; i += NTHR) {
        int row = i / 576, k = i - row * 576;
        int g = row >> 2, jr = row & 3;
        int r = g * HD + j0 + jr;
        sWA[i] = (k < IND) ? Wih1[r * IND + k] : Whh1[r * HD + (k - IND)];
    }
    for (int i = tid; i < 16 * 1024; i += NTHR) {
        int row = i >> 10, k = i & 1023;
        int g = row >> 2, jr = row & 3;
        int r = g * HD + j0 + jr;
        sWB[i] = (k < HD) ? Wih2[r * HD + k] : Whh2[r * HD + (k - HD)];
    }
    if (tid < 16) {
        int g = tid >> 2, jr = tid & 3;
        int r = g * HD + j0 + jr;
        sBA[tid] = bih1[r] + bhh1[r];
        sBB[tid] = bih2[r] + bhh2[r];
    }
    if (c < OUTD) {
        for (int i = tid; i < HD; i += NTHR) sWO[i] = Wout[c * HD + i];
        if (tid == 0) sBO[0] = bout[c];
    }

    // ---- prologue: transpose x to [t][k/4][b][k%4]; zero h buffers ----
    for (int t = c * (TSTEPS / NCTA); t < (c + 1) * (TSTEPS / NCTA); ++t) {
        for (int i = tid; i < BATCH * IND; i += NTHR) {
            int bb = i >> 6, k = i & 63;
            g_xT[((t * 16 + (k >> 2)) * 64 + bb) * 4 + (k & 3)] =
                x[bb * (TSTEPS * IND) + t * IND + k];
        }
    }
    {
        int base = c * NTHR + tid;   // 32768 threads cover HD*BATCH exactly
        g_h1[0][base] = 0.0f; g_h1[1][base] = 0.0f;
        g_h2[0][base] = 0.0f; g_h2[1][base] = 0.0f;
    }
    grid_barrier();

    // ---- recurrent main loop ----
    float c1 = 0.0f, c2 = 0.0f;
    const float* wA0 = sWA + (0 * 4 + jj) * 576;
    const float* wA1 = sWA + (1 * 4 + jj) * 576;
    const float* wA2 = sWA + (2 * 4 + jj) * 576;
    const float* wA3 = sWA + (3 * 4 + jj) * 576;
    const float* wB0 = sWB + (0 * 4 + jj) * 1024;
    const float* wB1 = sWB + (1 * 4 + jj) * 1024;
    const float* wB2 = sWB + (2 * 4 + jj) * 1024;
    const float* wB3 = sWB + (3 * 4 + jj) * 1024;
    const int hstore = c * 256 + b * 4 + jj;   // [j>>2=c][b][j&3=jj]

    for (int t = 0; t < TSTEPS; ++t) {
        const int rp = t & 1, wb = rp ^ 1;
        const float4* h1r = (const float4*)g_h1[rp];
        const float4* h2r = (const float4*)g_h2[rp];

        // ---- phase A: gates1 = x_t W_ih1^T + h1 W_hh1^T + bias ----
        float a0 = sBA[jj], a1 = sBA[4 + jj], a2 = sBA[8 + jj], a3 = sBA[12 + jj];
        const float4* xr = (const float4*)g_xT + t * (16 * 64);
#pragma unroll
        for (int k4 = 0; k4 < 16; ++k4) {
            float4 v = xr[k4 * 64 + b];
            DOT4(a0, v, wA0 + k4 * 4);
            DOT4(a1, v, wA1 + k4 * 4);
            DOT4(a2, v, wA2 + k4 * 4);
            DOT4(a3, v, wA3 + k4 * 4);
        }
#pragma unroll 4
        for (int k4 = 0; k4 < 128; ++k4) {
            float4 v = h1r[k4 * 64 + b];
            DOT4(a0, v, wA0 + 64 + k4 * 4);
            DOT4(a1, v, wA1 + 64 + k4 * 4);
            DOT4(a2, v, wA2 + 64 + k4 * 4);
            DOT4(a3, v, wA3 + 64 + k4 * 4);
        }
        {
            float iv = sigf(a0), fv = sigf(a1), gv = tanhf(a2), ov = sigf(a3);
            c1 = fv * c1 + iv * gv;
            g_h1[wb][hstore] = ov * tanhf(c1);
        }

        grid_barrier();   // publish h1(t); the ONLY barrier per step

        // ---- deferred output head y(t-1): reads h2(t-1) = g_h2[rp] ----
        if (t > 0) do_y(t - 1, h2r, c, b, jj, sWO, sBO, sRed, out);

        // ---- phase B: gates2 = h1(t) W_ih2^T + h2(t-1) W_hh2^T + bias ----
        float b0 = sBB[jj], b1 = sBB[4 + jj], b2 = sBB[8 + jj], b3 = sBB[12 + jj];
        const float4* h1w = (const float4*)g_h1[wb];
#pragma unroll 4
        for (int k4 = 0; k4 < 128; ++k4) {
            float4 v = h1w[k4 * 64 + b];
            DOT4(b0, v, wB0 + k4 * 4);
            DOT4(b1, v, wB1 + k4 * 4);
            DOT4(b2, v, wB2 + k4 * 4);
            DOT4(b3, v, wB3 + k4 * 4);
        }
#pragma unroll 4
        for (int k4 = 0; k4 < 128; ++k4) {
            float4 v = h2r[k4 * 64 + b];
            DOT4(b0, v, wB0 + 512 + k4 * 4);
            DOT4(b1, v, wB1 + 512 + k4 * 4);
            DOT4(b2, v, wB2 + 512 + k4 * 4);
            DOT4(b3, v, wB3 + 512 + k4 * 4);
        }
        {
            float iv = sigf(b0), fv = sigf(b1), gv = tanhf(b2), ov = sigf(b3);
            c2 = fv * c2 + iv * gv;
            g_h2[wb][hstore] = ov * tanhf(c2);
        }
    }

    grid_barrier();
    // final head: h2(T-1) lives in buffer ((T-1)&1)^1 == 0
    do_y(TSTEPS - 1, (const float4*)g_h2[0], c, b, jj, sWO, sBO, sRed, out);
}

extern "C" void kernel_launch(void* const* d_in, const int* in_sizes, int n_in,
                              void* d_out, int out_size) {
    const float* x    = (const float*)d_in[0];
    const float* Wih1 = (const float*)d_in[1];
    const float* Whh1 = (const float*)d_in[2];
    const float* bih1 = (const float*)d_in[3];
    const float* bhh1 = (const float*)d_in[4];
    const float* Wih2 = (const float*)d_in[5];
    const float* Whh2 = (const float*)d_in[6];
    const float* bih2 = (const float*)d_in[7];
    const float* bhh2 = (const float*)d_in[8];
    const float* Wout = (const float*)d_in[9];
    const float* bout = (const float*)d_in[10];
    float* out = (float*)d_out;

    size_t smem_bytes = (size_t)SMEM_N * sizeof(float);
    cudaFuncSetAttribute(lstm_persistent_kernel,
                         cudaFuncAttributeMaxDynamicSharedMemorySize,
                         (int)smem_bytes);
    lstm_persistent_kernel<<<NCTA, NTHR, smem_bytes>>>(
        x, Wih1, Whh1, bih1, bhh1, Wih2, Whh2, bih2, bhh2, Wout, bout, out);
}

// round 2
// speedup vs baseline: 1.4511x; 1.4511x over previous
#include <cuda_runtime.h>
#include <math.h>

#define BATCH 64
#define TSTEPS 1024
#define IND 64
#define HD 512
#define OUTD 64
#define NCTA 128
#define NTHR 256

// ---------------- persistent device state (no allocations allowed) ----------
__device__ float g_h1[2][HD * BATCH];      // layout: [k>>2][b][k&3]  (float4-friendly)
__device__ float g_h2[2][HD * BATCH];
__device__ float g_xT[TSTEPS * IND * BATCH]; // [t][k>>2][b][k&3]
__device__ unsigned g_gen;                  // barrier generation (monotonic across replays)
__device__ unsigned g_count;                // barrier arrival count (returns to 0)

// ---------------- grid-wide sense barrier (all 128 CTAs co-resident) --------
__device__ __forceinline__ void grid_barrier() {
    __syncthreads();
    if (threadIdx.x == 0) {
        __threadfence();                       // release: publish h writes
        volatile unsigned* vg = &g_gen;
        unsigned my = *vg;
        if (atomicAdd(&g_count, 1u) == NCTA - 1u) {
            g_count = 0u;                      // safe: nobody re-arrives until gen bumps
            __threadfence();
            *vg = my + 1u;
        } else {
            while (*vg == my) { }
        }
        __threadfence();                       // acquire
    }
    __syncthreads();
}

__device__ __forceinline__ float sigf(float x) { return 1.0f / (1.0f + __expf(-x)); }

// ---------------- shared memory layout (float offsets) ----------------------
#define O_WA   0        // 16 rows x 576  (W_ih1 | W_hh1) for this CTA's 16 gate rows
#define O_WB   9216     // 16 rows x 1024 (W_ih2 | W_hh2)
#define O_BA   25600    // 16 combined biases layer1
#define O_BB   25616    // 16 combined biases layer2
#define O_WO   25632    // 512: W_out row (CTAs 0..63)
#define O_BO   26144    // 1
#define O_RED  26148    // 4 x 64 reduction scratch for y head
#define SMEM_N 26404

#define DOT4(acc, v, wptr) do {                               \
    float4 w_ = *(const float4*)(wptr);                       \
    acc += (v).x * w_.x; acc += (v).y * w_.y;                 \
    acc += (v).z * w_.z; acc += (v).w * w_.w; } while (0)

// y(t) head: CTA c (<64) owns output column c; 4 threads per batch split K.
__device__ __forceinline__ void do_y(int t, const float4* __restrict__ h2v,
                                     int cblk, int b, int jj,
                                     const float* sWO, const float* sBO,
                                     float* sRed, float* __restrict__ out) {
    if (cblk < OUTD) {
        float p = 0.0f;
        const int k4b = jj * 32;
#pragma unroll 8
        for (int k4 = 0; k4 < 32; ++k4) {
            float4 v = h2v[(k4b + k4) * 64 + b];
            DOT4(p, v, sWO + (k4b + k4) * 4);
        }
        sRed[jj * 64 + b] = p;
    }
    __syncthreads();
    if (cblk < OUTD && jj == 0) {
        float y = sRed[b] + sRed[64 + b] + sRed[128 + b] + sRed[192 + b] + sBO[0];
        out[b * (TSTEPS * OUTD) + t * OUTD + cblk] = y;
    }
}

extern __shared__ float smem[];

__global__ void __launch_bounds__(NTHR, 1)
lstm_persistent_kernel(const float* __restrict__ x,
                       const float* __restrict__ Wih1, const float* __restrict__ Whh1,
                       const float* __restrict__ bih1, const float* __restrict__ bhh1,
                       const float* __restrict__ Wih2, const float* __restrict__ Whh2,
                       const float* __restrict__ bih2, const float* __restrict__ bhh2,
                       const float* __restrict__ Wout, const float* __restrict__ bout,
                       float* __restrict__ out) {
    float* sWA = smem + O_WA;
    float* sWB = smem + O_WB;
    float* sBA = smem + O_BA;
    float* sBB = smem + O_BB;
    float* sWO = smem + O_WO;
    float* sBO = smem + O_BO;
    float* sRed = smem + O_RED;

    const int tid = threadIdx.x;
    const int c   = blockIdx.x;       // CTA id: owns h columns j0..j0+3
    const int j0  = c * 4;
    const int b   = tid & 63;         // batch element (lanes 0..31 coalesce over b)
    const int jj  = tid >> 6;         // which of the 4 owned h columns

    // ---- load this CTA's weight slices into SMEM (once, persistent) ----
    for (int i = tid; i < 16 * 576; i += NTHR) {
        int row = i / 576, k = i - row * 576;
        int g = row >> 2, jr = row & 3;
        int r = g * HD + j0 + jr;
        sWA[i] = (k < IND) ? Wih1[r * IND + k] : Whh1[r * HD + (k - IND)];
    }
    for (int i = tid; i < 16 * 1024; i += NTHR) {
        int row = i >> 10, k = i & 1023;
        int g = row >> 2, jr = row & 3;
        int r = g * HD + j0 + jr;
        sWB[i] = (k < HD) ? Wih2[r * HD + k] : Whh2[r * HD + (k - HD)];
    }
    if (tid < 16) {
        int g = tid >> 2, jr = tid & 3;
        int r = g * HD + j0 + jr;
        sBA[tid] = bih1[r] + bhh1[r];
        sBB[tid] = bih2[r] + bhh2[r];
    }
    if (c < OUTD) {
        for (int i = tid; i < HD; i += NTHR) sWO[i] = Wout[c * HD + i];
        if (tid == 0) sBO[0] = bout[c];
    }

    // ---- prologue: transpose x to [t][k/4][b][k%4]; zero h buffers ----
    for (int t = c * (TSTEPS / NCTA); t < (c + 1) * (TSTEPS / NCTA); ++t) {
        for (int i = tid; i < BATCH * IND; i += NTHR) {
            int bb = i >> 6, k = i & 63;
            g_xT[((t * 16 + (k >> 2)) * 64 + bb) * 4 + (k & 3)] =
                x[bb * (TSTEPS * IND) + t * IND + k];
        }
    }
    {
        int base = c * NTHR + tid;   // 32768 threads cover HD*BATCH exactly
        g_h1[0][base] = 0.0f; g_h1[1][base] = 0.0f;
        g_h2[0][base] = 0.0f; g_h2[1][base] = 0.0f;
    }
    grid_barrier();

    // ---- recurrent main loop ----
    float c1 = 0.0f, c2 = 0.0f;
    const float* wA0 = sWA + (0 * 4 + jj) * 576;
    const float* wA1 = sWA + (1 * 4 + jj) * 576;
    const float* wA2 = sWA + (2 * 4 + jj) * 576;
    const float* wA3 = sWA + (3 * 4 + jj) * 576;
    const float* wB0 = sWB + (0 * 4 + jj) * 1024;
    const float* wB1 = sWB + (1 * 4 + jj) * 1024;
    const float* wB2 = sWB + (2 * 4 + jj) * 1024;
    const float* wB3 = sWB + (3 * 4 + jj) * 1024;
    const int hstore = c * 256 + b * 4 + jj;   // [j>>2=c][b][j&3=jj]

    for (int t = 0; t < TSTEPS; ++t) {
        const int rp = t & 1, wb = rp ^ 1;
        const float4* h1r = (const float4*)g_h1[rp];
        const float4* h2r = (const float4*)g_h2[rp];

        // ---- phase A: gates1 = x_t W_ih1^T + h1 W_hh1^T + bias ----
        float a0 = sBA[jj], a1 = sBA[4 + jj], a2 = sBA[8 + jj], a3 = sBA[12 + jj];
        const float4* xr = (const float4*)g_xT + t * (16 * 64);
#pragma unroll
        for (int k4 = 0; k4 < 16; ++k4) {
            float4 v = xr[k4 * 64 + b];
            DOT4(a0, v, wA0 + k4 * 4);
            DOT4(a1, v, wA1 + k4 * 4);
            DOT4(a2, v, wA2 + k4 * 4);
            DOT4(a3, v, wA3 + k4 * 4);
        }
#pragma unroll 4
        for (int k4 = 0; k4 < 128; ++k4) {
            float4 v = h1r[k4 * 64 + b];
            DOT4(a0, v, wA0 + 64 + k4 * 4);
            DOT4(a1, v, wA1 + 64 + k4 * 4);
            DOT4(a2, v, wA2 + 64 + k4 * 4);
            DOT4(a3, v, wA3 + 64 + k4 * 4);
        }
        {
            float iv = sigf(a0), fv = sigf(a1), gv = tanhf(a2), ov = sigf(a3);
            c1 = fv * c1 + iv * gv;
            g_h1[wb][hstore] = ov * tanhf(c1);
        }

        grid_barrier();   // publish h1(t); the ONLY barrier per step

        // ---- deferred output head y(t-1): reads h2(t-1) = g_h2[rp] ----
        if (t > 0) do_y(t - 1, h2r, c, b, jj, sWO, sBO, sRed, out);

        // ---- phase B: gates2 = h1(t) W_ih2^T + h2(t-1) W_hh2^T + bias ----
        float b0 = sBB[jj], b1 = sBB[4 + jj], b2 = sBB[8 + jj], b3 = sBB[12 + jj];
        const float4* h1w = (const float4*)g_h1[wb];
#pragma unroll 4
        for (int k4 = 0; k4 < 128; ++k4) {
            float4 v = h1w[k4 * 64 + b];
            DOT4(b0, v, wB0 + k4 * 4);
            DOT4(b1, v, wB1 + k4 * 4);
            DOT4(b2, v, wB2 + k4 * 4);
            DOT4(b3, v, wB3 + k4 * 4);
        }
#pragma unroll 4
        for (int k4 = 0; k4 < 128; ++k4) {
            float4 v = h2r[k4 * 64 + b];
            DOT4(b0, v, wB0 + 512 + k4 * 4);
            DOT4(b1, v, wB1 + 512 + k4 * 4);
            DOT4(b2, v, wB2 + 512 + k4 * 4);
            DOT4(b3, v, wB3 + 512 + k4 * 4);
        }
        {
            float iv = sigf(b0), fv = sigf(b1), gv = tanhf(b2), ov = sigf(b3);
            c2 = fv * c2 + iv * gv;
            g_h2[wb][hstore] = ov * tanhf(c2);
        }
    }

    grid_barrier();
    // final head: h2(T-1) lives in buffer ((T-1)&1)^1 == 0
    do_y(TSTEPS - 1, (const float4*)g_h2[0], c, b, jj, sWO, sBO, sRed, out);
}

extern "C" void kernel_launch(void* const* d_in, const int* in_sizes, int n_in,
                              void* d_out, int out_size) {
    const float* x    = (const float*)d_in[0];
    const float* Wih1 = (const float*)d_in[1];
    const float* Whh1 = (const float*)d_in[2];
    const float* bih1 = (const float*)d_in[3];
    const float* bhh1 = (const float*)d_in[4];
    const float* Wih2 = (const float*)d_in[5];
    const float* Whh2 = (const float*)d_in[6];
    const float* bih2 = (const float*)d_in[7];
    const float* bhh2 = (const float*)d_in[8];
    const float* Wout = (const float*)d_in[9];
    const float* bout = (const float*)d_in[10];
    float* out = (float*)d_out;

    size_t smem_bytes = (size_t)SMEM_N * sizeof(float);
    cudaFuncSetAttribute(lstm_persistent_kernel,
                         cudaFuncAttributeMaxDynamicSharedMemorySize,
                         (int)smem_bytes);
    lstm_persistent_kernel<<<NCTA, NTHR, smem_bytes>>>(
        x, Wih1, Whh1, bih1, bhh1, Wih2, Whh2, bih2, bhh2, Wout, bout, out);
}